// round 2
// baseline (speedup 1.0000x reference)
#include <cuda_runtime.h>

// Problem constants
#define B_ROWS 4096
#define D_IN   1024
#define H      512
#define NE     16
#define NU     33   // unit 0 = gate, 1..16 = m0 experts, 17..32 = m1 experts

// Scratch:
//  g_buf1     : layer-1 activations for all 33 units   [NU][B][H]   (277 MB)
//  g_gate2    : gate layer-2 activations               [B][H]       (8 MB)
//  g_dots_part: expert layer-2 fused-dot partials      [4][32][B]   (2 MB)
__device__ float g_buf1[(size_t)NU * B_ROWS * H];
__device__ float g_gate2[(size_t)B_ROWS * H];
__device__ float g_dots_part[4 * 32 * B_ROWS];

// SGEMM tiling
#define BM 128
#define BN 128
#define BK 16
#define TM 8
#define TN 8
#define NTHREADS 256

// ---------------------------------------------------------------------------
// Layer 1: g_buf1[u] = relu( x @ W1[u] + b1[u] ),  x shared across all units.
// ---------------------------------------------------------------------------
__global__ __launch_bounds__(NTHREADS)
void layer1_kernel(const float* __restrict__ x,
                   const float* __restrict__ gW,
                   const float* __restrict__ m0W,
                   const float* __restrict__ m1W,
                   const float* __restrict__ gb,
                   const float* __restrict__ m0b,
                   const float* __restrict__ m1b)
{
    const int u = blockIdx.z;
    const int K = D_IN;

    const float* Wbase;
    const float* bias;
    if (u == 0) {
        Wbase = gW;  bias = gb;
    } else if (u <= NE) {
        Wbase = m0W + (size_t)(u - 1) * K * H;
        bias  = m0b + (size_t)(u - 1) * H;
    } else {
        Wbase = m1W + (size_t)(u - 1 - NE) * K * H;
        bias  = m1b + (size_t)(u - 1 - NE) * H;
    }

    float* out = g_buf1 + (size_t)u * B_ROWS * H;

    const int row0 = blockIdx.y * BM;
    const int col0 = blockIdx.x * BN;

    __shared__ float As[BK][BM];
    __shared__ float Bs[BK][BN];

    const int tid = threadIdx.x;
    const int tx = tid & 15;
    const int ty = tid >> 4;

    float acc[TM][TN];
#pragma unroll
    for (int i = 0; i < TM; i++)
#pragma unroll
        for (int j = 0; j < TN; j++) acc[i][j] = 0.f;

    for (int k0 = 0; k0 < K; k0 += BK) {
#pragma unroll
        for (int it = 0; it < 2; it++) {
            int idx = tid + it * NTHREADS;
            int r   = idx >> 2;
            int c4  = (idx & 3) * 4;
            float4 v = *(const float4*)(x + (size_t)(row0 + r) * K + (k0 + c4));
            As[c4 + 0][r] = v.x;
            As[c4 + 1][r] = v.y;
            As[c4 + 2][r] = v.z;
            As[c4 + 3][r] = v.w;
        }
#pragma unroll
        for (int it = 0; it < 2; it++) {
            int idx = tid + it * NTHREADS;
            int r   = idx >> 5;
            int c4  = (idx & 31) * 4;
            *(float4*)&Bs[r][c4] =
                *(const float4*)(Wbase + (size_t)(k0 + r) * H + (col0 + c4));
        }
        __syncthreads();

#pragma unroll
        for (int k = 0; k < BK; k++) {
            float ra[TM], rb[TN];
#pragma unroll
            for (int i = 0; i < TM; i++) ra[i] = As[k][ty * TM + i];
#pragma unroll
            for (int j = 0; j < TN; j++) rb[j] = Bs[k][tx * TN + j];
#pragma unroll
            for (int i = 0; i < TM; i++)
#pragma unroll
                for (int j = 0; j < TN; j++)
                    acc[i][j] += ra[i] * rb[j];
        }
        __syncthreads();
    }

#pragma unroll
    for (int i = 0; i < TM; i++) {
        int m = row0 + ty * TM + i;
#pragma unroll
        for (int j = 0; j < TN; j += 4) {
            int n = col0 + tx * TN + j;
            float4 v;
            v.x = fmaxf(acc[i][j + 0] + bias[n + 0], 0.f);
            v.y = fmaxf(acc[i][j + 1] + bias[n + 1], 0.f);
            v.z = fmaxf(acc[i][j + 2] + bias[n + 2], 0.f);
            v.w = fmaxf(acc[i][j + 3] + bias[n + 3], 0.f);
            *(float4*)(out + (size_t)m * H + n) = v;
        }
    }
}

// ---------------------------------------------------------------------------
// Layer 2: h2 = relu( g_buf1[u] @ W2[u] + b2[u] )
//   u == 0 : store h2 into g_gate2
//   u >= 1 : fuse the Wo dot: partial[row] = sum_{n in tile} h2[row,n]*Wo[n]
//            -> g_dots_part[blockIdx.x][u-1][row]   (deterministic, no atomics)
// ---------------------------------------------------------------------------
__global__ __launch_bounds__(NTHREADS)
void layer2_kernel(const float* __restrict__ gW,
                   const float* __restrict__ m0W,
                   const float* __restrict__ m1W,
                   const float* __restrict__ gb,
                   const float* __restrict__ m0b,
                   const float* __restrict__ m1b,
                   const float* __restrict__ m0Wo,
                   const float* __restrict__ m1Wo)
{
    const int u = blockIdx.z;
    const int K = H;

    const float* A = g_buf1 + (size_t)u * B_ROWS * H;

    const float* Wbase;
    const float* bias;
    const float* wo = nullptr;
    if (u == 0) {
        Wbase = gW;  bias = gb;
    } else if (u <= NE) {
        Wbase = m0W + (size_t)(u - 1) * K * H;
        bias  = m0b + (size_t)(u - 1) * H;
        wo    = m0Wo + (size_t)(u - 1) * H;
    } else {
        Wbase = m1W + (size_t)(u - 1 - NE) * K * H;
        bias  = m1b + (size_t)(u - 1 - NE) * H;
        wo    = m1Wo + (size_t)(u - 1 - NE) * H;
    }

    const int row0 = blockIdx.y * BM;
    const int col0 = blockIdx.x * BN;

    __shared__ float As[BK][BM];
    __shared__ float Bs[BK][BN];

    const int tid = threadIdx.x;
    const int tx = tid & 15;
    const int ty = tid >> 4;

    float acc[TM][TN];
#pragma unroll
    for (int i = 0; i < TM; i++)
#pragma unroll
        for (int j = 0; j < TN; j++) acc[i][j] = 0.f;

    for (int k0 = 0; k0 < K; k0 += BK) {
#pragma unroll
        for (int it = 0; it < 2; it++) {
            int idx = tid + it * NTHREADS;
            int r   = idx >> 2;
            int c4  = (idx & 3) * 4;
            float4 v = *(const float4*)(A + (size_t)(row0 + r) * K + (k0 + c4));
            As[c4 + 0][r] = v.x;
            As[c4 + 1][r] = v.y;
            As[c4 + 2][r] = v.z;
            As[c4 + 3][r] = v.w;
        }
#pragma unroll
        for (int it = 0; it < 2; it++) {
            int idx = tid + it * NTHREADS;
            int r   = idx >> 5;
            int c4  = (idx & 31) * 4;
            *(float4*)&Bs[r][c4] =
                *(const float4*)(Wbase + (size_t)(k0 + r) * H + (col0 + c4));
        }
        __syncthreads();

#pragma unroll
        for (int k = 0; k < BK; k++) {
            float ra[TM], rb[TN];
#pragma unroll
            for (int i = 0; i < TM; i++) ra[i] = As[k][ty * TM + i];
#pragma unroll
            for (int j = 0; j < TN; j++) rb[j] = Bs[k][tx * TN + j];
#pragma unroll
            for (int i = 0; i < TM; i++)
#pragma unroll
                for (int j = 0; j < TN; j++)
                    acc[i][j] += ra[i] * rb[j];
        }
        __syncthreads();
    }

    if (u == 0) {
        // Gate: store full hidden row tile.
#pragma unroll
        for (int i = 0; i < TM; i++) {
            int m = row0 + ty * TM + i;
#pragma unroll
            for (int j = 0; j < TN; j += 4) {
                int n = col0 + tx * TN + j;
                float4 v;
                v.x = fmaxf(acc[i][j + 0] + bias[n + 0], 0.f);
                v.y = fmaxf(acc[i][j + 1] + bias[n + 1], 0.f);
                v.z = fmaxf(acc[i][j + 2] + bias[n + 2], 0.f);
                v.w = fmaxf(acc[i][j + 3] + bias[n + 3], 0.f);
                *(float4*)(g_gate2 + (size_t)m * H + n) = v;
            }
        }
    } else {
        // Expert: fused dot with Wo over this 128-column tile.
        float part[TM];
#pragma unroll
        for (int i = 0; i < TM; i++) {
            float p = 0.f;
#pragma unroll
            for (int j = 0; j < TN; j++) {
                int n = col0 + tx * TN + j;
                p += fmaxf(acc[i][j] + bias[n], 0.f) * wo[n];
            }
            part[i] = p;
        }
        // Reduce across the 16 tx lanes (contiguous lanes, width-16 butterflies).
#pragma unroll
        for (int i = 0; i < TM; i++) {
#pragma unroll
            for (int off = 8; off > 0; off >>= 1)
                part[i] += __shfl_xor_sync(0xffffffffu, part[i], off, 16);
        }
        if (tx == 0) {
#pragma unroll
            for (int i = 0; i < TM; i++) {
                int m = row0 + ty * TM + i;
                g_dots_part[((size_t)blockIdx.x * 32 + (u - 1)) * B_ROWS + m] = part[i];
            }
        }
    }
}

// ---------------------------------------------------------------------------
// Combine: gate logits from g_gate2, softmax, gather expert dots, weighted sum.
// One block (128 threads) per batch row.
// ---------------------------------------------------------------------------
__global__ __launch_bounds__(128)
void combine_kernel(const float* __restrict__ gWo,   // [512,16]
                    const float* __restrict__ gbo,   // [16]
                    const float* __restrict__ m0bo,  // [16]
                    const float* __restrict__ m1bo,  // [16]
                    float* __restrict__ out)         // [2*4096]
{
    const int b   = blockIdx.x;
    const int tid = threadIdx.x;

    __shared__ float sh[H];
    __shared__ float spart[8][16];
    __shared__ float sw[16];
    __shared__ float sdot[32];

    const float* hg = g_gate2 + (size_t)b * H;
    for (int k = tid; k < H; k += 128) sh[k] = hg[k];

    // Gather expert dots: sum of 4 column-block partials + output bias.
    if (tid < 32) {
        float d = 0.f;
#pragma unroll
        for (int p = 0; p < 4; p++)
            d += g_dots_part[((size_t)p * 32 + tid) * B_ROWS + b];
        d += (tid < NE) ? m0bo[tid] : m1bo[tid - NE];
        sdot[tid] = d;
    }
    __syncthreads();

    // Gate logits: 16 threads per expert column, 8 k-strides each.
    {
        int e  = tid & 15;
        int lk = tid >> 4;          // 0..7
        float p = 0.f;
        for (int k = lk; k < H; k += 8)
            p += sh[k] * gWo[k * NE + e];
        spart[lk][e] = p;
    }
    __syncthreads();
    if (tid < 16) {
        float s = gbo[tid];
#pragma unroll
        for (int l = 0; l < 8; l++) s += spart[l][tid];
        sw[tid] = s;
    }
    __syncthreads();
    if (tid == 0) {
        float mx = sw[0];
#pragma unroll
        for (int e = 1; e < 16; e++) mx = fmaxf(mx, sw[e]);
        float ssum = 0.f;
#pragma unroll
        for (int e = 0; e < 16; e++) { float v = expf(sw[e] - mx); sw[e] = v; ssum += v; }
        float inv = 1.f / ssum;

        float a0 = 0.f, a1 = 0.f;
#pragma unroll
        for (int e = 0; e < 16; e++) {
            float w = sw[e] * inv;
            a0 += w * sdot[e];
            a1 += w * sdot[16 + e];
        }
        out[b]          = a0;   // m0
        out[B_ROWS + b] = a1;   // m1
    }
}

extern "C" void kernel_launch(void* const* d_in, const int* in_sizes, int n_in,
                              void* d_out, int out_size)
{
    const float* x    = (const float*)d_in[0];
    const float* m0W1 = (const float*)d_in[1];
    const float* m0b1 = (const float*)d_in[2];
    const float* m0W2 = (const float*)d_in[3];
    const float* m0b2 = (const float*)d_in[4];
    const float* m0Wo = (const float*)d_in[5];
    const float* m0bo = (const float*)d_in[6];
    const float* m1W1 = (const float*)d_in[7];
    const float* m1b1 = (const float*)d_in[8];
    const float* m1W2 = (const float*)d_in[9];
    const float* m1b2 = (const float*)d_in[10];
    const float* m1Wo = (const float*)d_in[11];
    const float* m1bo = (const float*)d_in[12];
    const float* gW1  = (const float*)d_in[13];
    const float* gb1  = (const float*)d_in[14];
    const float* gW2  = (const float*)d_in[15];
    const float* gb2  = (const float*)d_in[16];
    const float* gWo  = (const float*)d_in[17];
    const float* gbo  = (const float*)d_in[18];
    float* out = (float*)d_out;

    dim3 grid(H / BN, B_ROWS / BM, NU);   // (4, 32, 33)

    layer1_kernel<<<grid, NTHREADS>>>(x, gW1, m0W1, m1W1, gb1, m0b1, m1b1);
    layer2_kernel<<<grid, NTHREADS>>>(gW2, m0W2, m1W2, gb2, m0b2, m1b2, m0Wo, m1Wo);
    combine_kernel<<<B_ROWS, 128>>>(gWo, gbo, m0bo, m1bo, out);
}